// round 4
// baseline (speedup 1.0000x reference)
#include <cuda_runtime.h>
#include <math.h>
#include <float.h>

#define Bn 128
#define Tn 64
#define Cn 6625
#define Ln 25
#define Kn 6
#define Sn (2*Ln + 1)          // 51
#define NEGF (-1e30f)
#define ALPHA_C 0.1f
#define TAIL_C 0.01f
#define NSEQ (Bn + Bn*Kn)      // 896
#define NCAND 128
#define FULLM 0xffffffffu
#define VRPT 7                 // 7*256*4 = 7168 >= 6625

// ---------------- device scratch ----------------
__device__ float g_logZ[Bn*Tn];
__device__ float g_m1[Bn*Tn];
__device__ float g_m2[Bn*Tn];
__device__ int   g_i1[Bn*Tn];
__device__ int   g_i2[Bn*Tn];
__device__ float g_lpb0[Bn*Tn];
__device__ float g_conf[Bn];
__device__ float g_nll[NSEQ];
__device__ unsigned int g_ctr;

// fast log-add-exp (MUFU)
__device__ __forceinline__ float lae(float a, float b) {
    float mx = fmaxf(a, b), mn = fminf(a, b);
    return mx + __logf(1.f + __expf(mn - mx));
}

// orderable float key
__device__ __forceinline__ unsigned int fkey(float v) {
    unsigned int b = __float_as_uint(v);
    return (b & 0x80000000u) ? ~b : (b | 0x80000000u);
}
__device__ __forceinline__ float fkey_inv(unsigned int k) {
    unsigned int b = (k & 0x80000000u) ? (k ^ 0x80000000u) : ~k;
    return __uint_as_float(b);
}
__device__ __forceinline__ unsigned long long pack_cand(float v, int c) {
    return ((unsigned long long)fkey(v) << 32) |
           (unsigned long long)(0xFFFFFFFFu - (unsigned)c);
}
__device__ __forceinline__ void top2_ins(unsigned long long& t1, unsigned long long& t2,
                                         unsigned long long pk) {
    unsigned long long lo = (pk > t1) ? t1 : pk;
    t1 = (pk > t1) ? pk : t1;
    t2 = (lo > t2) ? lo : t2;
}
__device__ __forceinline__ void top2_merge(unsigned long long& a1, unsigned long long& a2,
                                           unsigned long long b1, unsigned long long b2) {
    unsigned long long n1 = (a1 > b1) ? a1 : b1;
    unsigned long long lo = (a1 > b1) ? b1 : a1;
    unsigned long long m2 = (a2 > b2) ? a2 : b2;
    a2 = (m2 > lo) ? m2 : lo;
    a1 = n1;
}

// ---------------- kernel 1: row stats, float4 vectorized ----------------
__global__ __launch_bounds__(256) void k_rowstats(const float* __restrict__ preds) {
    int row = blockIdx.x;
    const float* p = preds + (long long)row * Cn;
    int tid = threadIdx.x;
    int lane = tid & 31, wid = tid >> 5;

    if (row == 0 && tid == 0) g_ctr = 0u;   // reset fused-kernel counter each call

    // alignment peel: element e is 16B-aligned when (row*Cn + e) % 4 == 0
    int a0 = (4 - ((row * Cn) & 3)) & 3;    // leading scalar count (0..3)
    int nv = (Cn - a0) >> 2;                // float4 count
    int rem = Cn - a0 - (nv << 2);          // tail scalar count (0..3)
    const float4* pv = (const float4*)(p + a0);

    float rv[VRPT * 4];
    float pe, tv;
    float mx = -FLT_MAX;
    unsigned long long t1 = 0ull, t2 = 0ull;

    // peel scalars (c = tid, tid < a0 <= 3)
    pe = (tid < a0) ? __ldg(p + tid) : -FLT_MAX;
    if (tid < a0) {
        mx = fmaxf(mx, pe);
        if (tid >= 1) top2_ins(t1, t2, pack_cand(pe, tid));
    }
    // tail scalars (c = a0 + 4*nv + tid)
    {
        int c = a0 + (nv << 2) + tid;
        tv = (tid < rem) ? __ldg(p + c) : -FLT_MAX;
        if (tid < rem) {
            mx = fmaxf(mx, tv);
            top2_ins(t1, t2, pack_cand(tv, c));     // c >= 6620, always >= 1
        }
    }
    // vector body
#pragma unroll
    for (int k = 0; k < VRPT; k++) {
        int idx = tid + k * 256;
        bool ok = (idx < nv);
        float4 v = ok ? __ldg(pv + idx) : make_float4(-FLT_MAX,-FLT_MAX,-FLT_MAX,-FLT_MAX);
        rv[k*4+0] = v.x; rv[k*4+1] = v.y; rv[k*4+2] = v.z; rv[k*4+3] = v.w;
        if (ok) {
            int c = a0 + (idx << 2);
            mx = fmaxf(fmaxf(mx, fmaxf(v.x, v.y)), fmaxf(v.z, v.w));
            if (c >= 1) top2_ins(t1, t2, pack_cand(v.x, c));
            top2_ins(t1, t2, pack_cand(v.y, c + 1));
            top2_ins(t1, t2, pack_cand(v.z, c + 2));
            top2_ins(t1, t2, pack_cand(v.w, c + 3));
        }
    }

    // warp reduce
#pragma unroll
    for (int off = 16; off > 0; off >>= 1) {
        mx = fmaxf(mx, __shfl_xor_sync(FULLM, mx, off));
        unsigned long long o1 = __shfl_xor_sync(FULLM, t1, off);
        unsigned long long o2 = __shfl_xor_sync(FULLM, t2, off);
        top2_merge(t1, t2, o1, o2);
    }

    __shared__ float s_mx[8], s_s[8];
    __shared__ unsigned long long s_t1[8], s_t2[8];
    __shared__ float s_bmx, s_sum;
    if (lane == 0) { s_mx[wid] = mx; s_t1[wid] = t1; s_t2[wid] = t2; }
    __syncthreads();
    if (wid == 0) {
        float m = (lane < 8) ? s_mx[lane] : -FLT_MAX;
        unsigned long long u1 = (lane < 8) ? s_t1[lane] : 0ull;
        unsigned long long u2 = (lane < 8) ? s_t2[lane] : 0ull;
#pragma unroll
        for (int off = 4; off > 0; off >>= 1) {
            m = fmaxf(m, __shfl_xor_sync(FULLM, m, off));
            unsigned long long o1 = __shfl_xor_sync(FULLM, u1, off);
            unsigned long long o2 = __shfl_xor_sync(FULLM, u2, off);
            top2_merge(u1, u2, o1, o2);
        }
        if (lane == 0) { s_bmx = m; s_t1[0] = u1; s_t2[0] = u2; }
    }
    __syncthreads();

    float bmx = s_bmx;
    float sum = __expf(pe - bmx) + __expf(tv - bmx);   // -FLT_MAX pads -> 0
#pragma unroll
    for (int k = 0; k < VRPT * 4; k++) sum += __expf(rv[k] - bmx);

#pragma unroll
    for (int off = 16; off > 0; off >>= 1)
        sum += __shfl_xor_sync(FULLM, sum, off);
    if (lane == 0) s_s[wid] = sum;
    __syncthreads();
    if (wid == 0) {
        float sm = (lane < 8) ? s_s[lane] : 0.f;
#pragma unroll
        for (int off = 4; off > 0; off >>= 1) sm += __shfl_xor_sync(FULLM, sm, off);
        if (lane == 0) s_sum = sm;
    }
    __syncthreads();

    if (tid == 0) {
        float lz = bmx + __logf(s_sum);
        unsigned long long u1 = s_t1[0], u2 = s_t2[0];
        g_logZ[row] = lz;
        g_m1[row] = fkey_inv((unsigned int)(u1 >> 32));
        g_m2[row] = fkey_inv((unsigned int)(u2 >> 32));
        g_i1[row] = (int)(0xFFFFFFFFu - (unsigned int)(u1 & 0xFFFFFFFFull));
        g_i2[row] = (int)(0xFFFFFFFFu - (unsigned int)(u2 & 0xFFFFFFFFull));
        g_lpb0[row] = __ldg(p) - lz;
    }
}

// ---------------- kernel 2: fused gather + beam + CTC + final ----------------
__global__ __launch_bounds__(128) void k_main(
    const float* __restrict__ preds,
    const int* __restrict__ text,
    const int* __restrict__ preds_size,
    const int* __restrict__ length,
    const int* __restrict__ smooth_text,
    const int* __restrict__ smooth_length,
    float* __restrict__ out)
{
    int tid = threadIdx.x;

    // beam-block shared
    __shared__ float stbl[Tn * NCAND];      // 32KB
    __shared__ float sm1[Tn], sm2[Tn], slz[Tn], slpb[Tn];
    __shared__ int   si1[Tn], si2[Tn];
    // ctc-block shared
    __shared__ int   ext[Sn], skipf[Sn];
    __shared__ float bufA[Sn + 2], bufB[Sn + 2];
    __shared__ float slz2[Tn];
    // epilogue
    __shared__ unsigned int s_old;
    __shared__ float red[NCAND];

    if (blockIdx.x < Bn) {
        // ================= beam-1 prefix search, inline gather =================
        int b = blockIdx.x;
        if (tid < Tn) {
            int r = b * Tn + tid;
            sm1[tid] = g_m1[r]; sm2[tid] = g_m2[r];
            si1[tid] = g_i1[r]; si2[tid] = g_i2[r];
            slz[tid] = g_logZ[r]; slpb[tid] = g_lpb0[r];
        }
        __syncthreads();

        // gather: thread j owns candidate j; loop t
        int ch = (tid < Tn) ? si1[tid] : si2[tid - Tn];
        const float* pb = preds + (long long)b * Tn * Cn + ch;
#pragma unroll 8
        for (int t = 0; t < Tn; t++)
            stbl[t * NCAND + tid] = __ldg(pb + (long long)t * Cn) - slz[t];
        __syncthreads();

        if (tid == 0) {
            float lpb = 0.f, lpnb = NEGF;
            int last = -1, lastj = 0;
            for (int t = 0; t < Tn; t++) {
                float lp_last = (last >= 0) ? stbl[t * NCAND + lastj] : NEGF;
                float tot    = lae(lpb, lpnb);
                float new_pb = tot + slpb[t];
                float rep    = (last >= 0) ? (lpnb + lp_last) : NEGF;
                float keep   = lae(new_pb, rep);
                float lpm1 = sm1[t] - slz[t];
                float lpm2 = sm2[t] - slz[t];
                float best_ext; int best_c, best_j;
                if (si1[t] != last) {
                    best_ext = tot + lpm1; best_c = si1[t]; best_j = t;
                } else {
                    float cA = lpb + lpm1;
                    float cB = tot + lpm2;
                    if (cA > cB || (cA == cB && last < si2[t])) {
                        best_ext = cA; best_c = last; best_j = t;
                    } else {
                        best_ext = cB; best_c = si2[t]; best_j = Tn + t;
                    }
                }
                bool take = best_ext > keep;
                lpb   = take ? NEGF     : new_pb;
                lpnb  = take ? best_ext : rep;
                last  = take ? best_c   : last;
                lastj = take ? best_j   : lastj;
            }
            float score = lae(lpb, lpnb);
            g_conf[b] = __expf(score / (float)Tn);
        }
    } else {
        // ================= CTC forward (block per sequence) =================
        int n = blockIdx.x - Bn;
        int b, tlen, ilen;
        const int* lab;
        if (n < Bn) {
            b = n; lab = text + n * Ln;
            tlen = length[n]; ilen = preds_size[n];
        } else {
            int m = n - Bn;
            b = m / Kn; lab = smooth_text + m * Ln;
            tlen = smooth_length[m]; ilen = Tn;
        }

        int s = tid;
        if (s < Sn) ext[s] = (s & 1) ? lab[(s - 1) >> 1] : 0;
        if (s < 2) { bufA[s] = NEGF; bufB[s] = NEGF; }
        if (s >= 64 && s < 64 + Tn) slz2[s - 64] = g_logZ[b * Tn + (s - 64)];
        __syncthreads();
        if (s < Sn) skipf[s] = ((s & 1) && s >= 3 && ext[s] != ext[s - 2]) ? 1 : 0;

        const float* pp = preds + (long long)b * Tn * Cn;
        int ech = (s < Sn) ? ext[s] : 0;

        if (s < Sn) {
            float lz0 = slz2[0];
            bufA[s + 2] = (s < 2) ? (__ldg(pp + ech) - lz0) : NEGF;
        }
        __syncthreads();

        float pf[8];
#pragma unroll
        for (int q = 0; q < 8; q++) {
            int tq = 1 + q;
            pf[q] = (s < Sn && tq < Tn) ? __ldg(pp + (long long)tq * Cn + ech) : 0.f;
        }

        float* cur = bufA;
        float* nxt = bufB;
#pragma unroll 8
        for (int t = 1; t < Tn; t++) {
            float raw = pf[(t - 1) & 7];
            int tpre = t + 8;
            if (s < Sn && tpre < Tn)
                pf[(t - 1) & 7] = __ldg(pp + (long long)tpre * Cn + ech);
            if (s < Sn) {
                float a  = cur[s + 2];
                float a1 = cur[s + 1];
                float a2 = skipf[s] ? cur[s] : NEGF;
                float m  = fmaxf(a, fmaxf(a1, a2));
                float tot = m + __logf(__expf(a - m) + __expf(a1 - m) + __expf(a2 - m));
                float lp  = raw - slz2[t];
                nxt[s + 2] = (t < ilen) ? (tot + lp) : a;
            }
            __syncthreads();
            float* tmp = cur; cur = nxt; nxt = tmp;
        }

        if (s == 0) {
            int il = 2 * tlen;
            float ab = cur[il + 2];
            float ac = cur[il + 1];
            float nll = -lae(ab, ac);
            if (nll > 1e29f) nll = 0.f;
            g_nll[n] = nll;
        }
    }

    // ================= last-block final reduction =================
    __syncthreads();
    __threadfence();
    if (tid == 0) s_old = atomicAdd(&g_ctr, 1u);
    __syncthreads();
    if (s_old == (unsigned)(Bn + NSEQ - 1)) {
        volatile float* vnll  = g_nll;
        volatile float* vconf = g_conf;
        int b = tid;                         // 0..127
        float lm = vnll[b] / (float)__ldg(length + b);
        float lc = 0.f;
#pragma unroll
        for (int k = 0; k < Kn; k++)
            lc += vnll[Bn + b * Kn + k] / (float)__ldg(smooth_length + b * Kn + k);
        lc *= (1.f / (float)Kn);
        float conf = vconf[b];
        float omc = 1.f - conf;
        float r = TAIL_C + (1.f - TAIL_C) * omc * omc;
        red[b] = lm + ALPHA_C * r * lc;
        __syncthreads();
        for (int off = Bn / 2; off > 0; off >>= 1) {
            if (b < off) red[b] += red[b + off];
            __syncthreads();
        }
        if (b == 0) out[0] = red[0] / (float)Bn;
    }
}

// ---------------- launch ----------------
extern "C" void kernel_launch(void* const* d_in, const int* in_sizes, int n_in,
                              void* d_out, int out_size) {
    const float* preds         = (const float*)d_in[0];
    const int*   text          = (const int*)d_in[1];
    const int*   preds_size    = (const int*)d_in[2];
    const int*   length        = (const int*)d_in[3];
    const int*   smooth_text   = (const int*)d_in[4];
    const int*   smooth_length = (const int*)d_in[5];
    float* out = (float*)d_out;

    k_rowstats<<<Bn * Tn, 256>>>(preds);
    k_main    <<<Bn + NSEQ, 128>>>(preds, text, preds_size, length,
                                   smooth_text, smooth_length, out);
}

// round 5
// speedup vs baseline: 1.2109x; 1.2109x over previous
#include <cuda_runtime.h>
#include <math.h>
#include <float.h>

#define Bn 128
#define Tn 64
#define Cn 6625
#define Ln 25
#define Kn 6
#define Sn (2*Ln + 1)
#define NEGF (-1e30f)
#define ALPHA_C 0.1f
#define TAIL_C 0.01f
#define NSEQ (Bn + Bn*Kn)      // 896
#define NCAND 128
#define FULLM 0xffffffffu
#define VRPT 7                 // 7*256*4 = 7168 >= 6625
#define CTCB (NSEQ/4)          // 224 blocks, 4 warps each

// ---------------- device scratch ----------------
__device__ float g_logZ[Bn*Tn];
__device__ float g_m1[Bn*Tn];
__device__ float g_m2[Bn*Tn];
__device__ int   g_i1[Bn*Tn];
__device__ int   g_i2[Bn*Tn];
__device__ float g_lpb0[Bn*Tn];
__device__ float g_conf[Bn];
__device__ float g_nll[NSEQ];
__device__ unsigned int g_ctr;

__device__ __forceinline__ float lae(float a, float b) {
    float mx = fmaxf(a, b), mn = fminf(a, b);
    return mx + __logf(1.f + __expf(mn - mx));
}
__device__ __forceinline__ float lae3(float a, float b, float c) {
    float m = fmaxf(a, fmaxf(b, c));
    return m + __logf(__expf(a - m) + __expf(b - m) + __expf(c - m));
}
__device__ __forceinline__ unsigned int fkey(float v) {
    unsigned int b = __float_as_uint(v);
    return (b & 0x80000000u) ? ~b : (b | 0x80000000u);
}

// smallest class index in this thread's registers with value == target (c>=1, c!=excl)
__device__ __forceinline__ int scan_idx(const float* rv, float pe, float tv,
        int tid, int a0, int nv, int rem, float target, int excl) {
    int best = 0x7fffffff;
    if (tid >= 1 && tid < a0 && pe == target && tid != excl) best = tid;
#pragma unroll
    for (int k = 0; k < VRPT; k++) {
        int idx = tid + k * 256;
        if (idx < nv) {
            int cb = a0 + (idx << 2);
#pragma unroll
            for (int j = 0; j < 4; j++) {
                int c = cb + j;
                if (c >= 1 && c != excl && rv[k*4+j] == target && c < best) best = c;
            }
        }
    }
    int ct = a0 + (nv << 2) + tid;
    if (tid < rem && tv == target && ct != excl && ct < best) best = ct;
    return best;
}
// max over this thread's registers with c>=1, c != excl
__device__ __forceinline__ float scan_max_excl(const float* rv, float pe, float tv,
        int tid, int a0, int nv, int rem, int excl) {
    float m = -FLT_MAX;
    if (tid >= 1 && tid < a0 && tid != excl) m = fmaxf(m, pe);
#pragma unroll
    for (int k = 0; k < VRPT; k++) {
        int idx = tid + k * 256;
        if (idx < nv) {
            int cb = a0 + (idx << 2);
#pragma unroll
            for (int j = 0; j < 4; j++) {
                int c = cb + j;
                if (c >= 1 && c != excl) m = fmaxf(m, rv[k*4+j]);
            }
        }
    }
    int ct = a0 + (nv << 2) + tid;
    if (tid < rem && ct != excl) m = fmaxf(m, tv);
    return m;
}

// ---------------- kernel 1: row stats ----------------
__global__ __launch_bounds__(256) void k_rowstats(const float* __restrict__ preds) {
    int row = blockIdx.x;
    const float* p = preds + (long long)row * Cn;
    int tid = threadIdx.x;
    int lane = tid & 31, wid = tid >> 5;

    if (row == 0 && tid == 0) g_ctr = 0u;

    int a0 = (4 - ((row * Cn) & 3)) & 3;
    int nv = (Cn - a0) >> 2;
    int rem = Cn - a0 - (nv << 2);
    const float4* pv = (const float4*)(p + a0);

    float rv[VRPT * 4];
    float mx = -FLT_MAX;     // overall max (for LSE)
    float cmx = -FLT_MAX;    // candidate max (c>=1)

    float pe = (tid < a0) ? __ldg(p + tid) : -FLT_MAX;
    mx = fmaxf(mx, pe);
    if (tid >= 1) cmx = fmaxf(cmx, pe);      // tid==0 peel is blank

    int ctail = a0 + (nv << 2) + tid;
    float tv = (tid < rem) ? __ldg(p + ctail) : -FLT_MAX;
    mx = fmaxf(mx, tv);
    cmx = fmaxf(cmx, tv);

#pragma unroll
    for (int k = 0; k < VRPT; k++) {
        int idx = tid + k * 256;
        bool ok = (idx < nv);
        float4 v = ok ? __ldg(pv + idx) : make_float4(-FLT_MAX,-FLT_MAX,-FLT_MAX,-FLT_MAX);
        rv[k*4+0] = v.x; rv[k*4+1] = v.y; rv[k*4+2] = v.z; rv[k*4+3] = v.w;
        mx = fmaxf(fmaxf(mx, fmaxf(v.x, v.y)), fmaxf(v.z, v.w));
        float vx = (a0 == 0 && idx == 0) ? -FLT_MAX : v.x;   // exclude c==0
        cmx = fmaxf(fmaxf(cmx, fmaxf(vx, v.y)), fmaxf(v.z, v.w));
    }

    // block reduce: overall max + candidate argmax owner
    unsigned long long key = ((unsigned long long)fkey(cmx) << 32) | (unsigned)tid;
#pragma unroll
    for (int off = 16; off > 0; off >>= 1) {
        mx = fmaxf(mx, __shfl_xor_sync(FULLM, mx, off));
        unsigned long long o = __shfl_xor_sync(FULLM, key, off);
        key = (o > key) ? o : key;
    }
    __shared__ float s_mx[8], s_s[8];
    __shared__ unsigned long long s_k[8];
    __shared__ float s_bmx, s_sum, s_m1, s_m2, s_loc2;
    __shared__ int s_i1, s_i2;
    __shared__ unsigned long long s_key;
    if (lane == 0) { s_mx[wid] = mx; s_k[wid] = key; }
    __syncthreads();
    if (wid == 0) {
        float m = (lane < 8) ? s_mx[lane] : -FLT_MAX;
        unsigned long long u = (lane < 8) ? s_k[lane] : 0ull;
#pragma unroll
        for (int off = 4; off > 0; off >>= 1) {
            m = fmaxf(m, __shfl_xor_sync(FULLM, m, off));
            unsigned long long o = __shfl_xor_sync(FULLM, u, off);
            u = (o > u) ? o : u;
        }
        if (lane == 0) { s_bmx = m; s_key = u; }
    }
    __syncthreads();

    int T1 = (int)(s_key & 0xFFFFFFFFull);
    if (tid == T1) {
        float m1 = cmx;                       // this thread's cmx == block cmx
        s_m1 = m1;
        int i1 = scan_idx(rv, pe, tv, tid, a0, nv, rem, m1, -1);
        s_i1 = i1;
        s_loc2 = scan_max_excl(rv, pe, tv, tid, a0, nv, rem, i1);
    }
    __syncthreads();

    // phase 2: second max
    float val2 = (tid == T1) ? s_loc2 : cmx;
    unsigned long long key2 = ((unsigned long long)fkey(val2) << 32) | (unsigned)tid;
#pragma unroll
    for (int off = 16; off > 0; off >>= 1) {
        unsigned long long o = __shfl_xor_sync(FULLM, key2, off);
        key2 = (o > key2) ? o : key2;
    }
    if (lane == 0) s_k[wid] = key2;
    __syncthreads();
    if (wid == 0) {
        unsigned long long u = (lane < 8) ? s_k[lane] : 0ull;
#pragma unroll
        for (int off = 4; off > 0; off >>= 1) {
            unsigned long long o = __shfl_xor_sync(FULLM, u, off);
            u = (o > u) ? o : u;
        }
        if (lane == 0) s_key = u;
    }
    __syncthreads();
    int T2 = (int)(s_key & 0xFFFFFFFFull);
    if (tid == T2) {
        float m2 = (tid == T1) ? s_loc2 : cmx;
        s_m2 = m2;
        s_i2 = scan_idx(rv, pe, tv, tid, a0, nv, rem, m2, s_i1);
    }

    // exp-sum pass
    float bmx = s_bmx;
    float sum = __expf(pe - bmx) + __expf(tv - bmx);
#pragma unroll
    for (int k = 0; k < VRPT * 4; k++) sum += __expf(rv[k] - bmx);
#pragma unroll
    for (int off = 16; off > 0; off >>= 1)
        sum += __shfl_xor_sync(FULLM, sum, off);
    if (lane == 0) s_s[wid] = sum;
    __syncthreads();
    if (wid == 0) {
        float sm = (lane < 8) ? s_s[lane] : 0.f;
#pragma unroll
        for (int off = 4; off > 0; off >>= 1) sm += __shfl_xor_sync(FULLM, sm, off);
        if (lane == 0) s_sum = sm;
    }
    __syncthreads();

    if (tid == 0) {
        float lz = bmx + __logf(s_sum);
        g_logZ[row] = lz;
        g_m1[row] = s_m1;  g_i1[row] = s_i1;
        g_m2[row] = s_m2;  g_i2[row] = s_i2;
        g_lpb0[row] = __ldg(p) - lz;
    }
}

// ---------------- kernel 2: beam-1 prefix search ----------------
__global__ __launch_bounds__(128) void k_beam(const float* __restrict__ preds) {
    int tid = threadIdx.x;
    int b = blockIdx.x;
    __shared__ float stbl[Tn * NCAND];
    __shared__ float sm1[Tn], sm2[Tn], slz[Tn], slpb[Tn];
    __shared__ int   si1[Tn], si2[Tn];

    if (tid < Tn) {
        int r = b * Tn + tid;
        sm1[tid] = g_m1[r]; sm2[tid] = g_m2[r];
        si1[tid] = g_i1[r]; si2[tid] = g_i2[r];
        slz[tid] = g_logZ[r]; slpb[tid] = g_lpb0[r];
    }
    __syncthreads();

    int ch = (tid < Tn) ? si1[tid] : si2[tid - Tn];
    const float* pb = preds + (long long)b * Tn * Cn + ch;
#pragma unroll 8
    for (int t = 0; t < Tn; t++)
        stbl[t * NCAND + tid] = __ldg(pb + (long long)t * Cn) - slz[t];
    __syncthreads();

    if (tid == 0) {
        float lpb = 0.f, lpnb = NEGF;
        int last = -1, lastj = 0;
        for (int t = 0; t < Tn; t++) {
            float lp_last = (last >= 0) ? stbl[t * NCAND + lastj] : NEGF;
            float tot    = lae(lpb, lpnb);
            float new_pb = tot + slpb[t];
            float rep    = (last >= 0) ? (lpnb + lp_last) : NEGF;
            float keep   = lae(new_pb, rep);
            float lpm1 = sm1[t] - slz[t];
            float lpm2 = sm2[t] - slz[t];
            float best_ext; int best_c, best_j;
            if (si1[t] != last) {
                best_ext = tot + lpm1; best_c = si1[t]; best_j = t;
            } else {
                float cA = lpb + lpm1;
                float cB = tot + lpm2;
                if (cA > cB || (cA == cB && last < si2[t])) {
                    best_ext = cA; best_c = last; best_j = t;
                } else {
                    best_ext = cB; best_c = si2[t]; best_j = Tn + t;
                }
            }
            bool take = best_ext > keep;
            lpb   = take ? NEGF     : new_pb;
            lpnb  = take ? best_ext : rep;
            last  = take ? best_c   : last;
            lastj = take ? best_j   : lastj;
        }
        g_conf[b] = __expf(lae(lpb, lpnb) / (float)Tn);
    }
}

// ---------------- kernel 3: warp-per-sequence CTC + final reduction ----------------
__global__ __launch_bounds__(128) void k_ctc(
    const float* __restrict__ preds,
    const int* __restrict__ text,
    const int* __restrict__ preds_size,
    const int* __restrict__ length,
    const int* __restrict__ smooth_text,
    const int* __restrict__ smooth_length,
    float* __restrict__ out)
{
    int tid = threadIdx.x;
    int warp = tid >> 5, l = tid & 31;
    int n = blockIdx.x * 4 + warp;          // < 896 exactly

    int b, tlen, ilen;
    const int* lab;
    if (n < Bn) {
        b = n; lab = text + n * Ln;
        tlen = __ldg(length + n); ilen = __ldg(preds_size + n);
    } else {
        int m = n - Bn;
        b = m / Kn; lab = smooth_text + m * Ln;
        tlen = __ldg(smooth_length + m); ilen = Tn;
    }

    // lane l owns states s0=2l (l<=25), s1=2l+1 (l<=24)
    int lab_l = (l < Ln) ? __ldg(lab + l) : 0;
    int lab_p = __shfl_up_sync(FULLM, lab_l, 1);
    bool skip1 = (l >= 1) && (l < Ln) && (lab_l != lab_p);
    bool v0 = (l <= 25), v1 = (l <= 24);
    bool ldok = (l < Ln);

    float lzA  = __ldg(g_logZ + b*Tn + l);
    float lzB  = __ldg(g_logZ + b*Tn + 32 + l);
    float lpbA = __ldg(g_lpb0 + b*Tn + l);
    float lpbB = __ldg(g_lpb0 + b*Tn + 32 + l);

    const float* base = preds + (long long)b * Tn * Cn + lab_l;

    float lz0   = __shfl_sync(FULLM, lzA, 0);
    float lpb00 = __shfl_sync(FULLM, lpbA, 0);
    float c0 = ldok ? __ldg(base) : 0.f;
    float a0 = (l == 0) ? lpb00 : NEGF;
    float a1 = (l == 0) ? (c0 - lz0) : NEGF;

    float pf[8];
#pragma unroll
    for (int q = 0; q < 8; q++)
        pf[q] = ldok ? __ldg(base + (long long)(1 + q) * Cn) : 0.f;

#pragma unroll 4
    for (int t = 1; t < Tn; t++) {
        float raw = pf[(t - 1) & 7];
        if (ldok && t + 8 < Tn)
            pf[(t - 1) & 7] = __ldg(base + (long long)(t + 8) * Cn);

        float lzt  = __shfl_sync(FULLM, (t < 32) ? lzA  : lzB,  t & 31);
        float lpbt = __shfl_sync(FULLM, (t < 32) ? lpbA : lpbB, t & 31);

        float p1 = __shfl_up_sync(FULLM, a1, 1);    // alpha[2l-1]
        if (l == 0) p1 = NEGF;

        float tot0 = lae(a0, p1);                           // s0: alpha[2l], alpha[2l-1]
        float tot1 = lae3(a1, a0, skip1 ? p1 : NEGF);       // s1: alpha[2l+1], alpha[2l], alpha[2l-1]
        float n0 = tot0 + lpbt;
        float n1 = tot1 + (raw - lzt);
        bool act = (t < ilen);
        a0 = act ? (v0 ? n0 : NEGF) : a0;
        a1 = act ? (v1 ? n1 : NEGF) : a1;
    }

    float ab = __shfl_sync(FULLM, a0, tlen);        // state 2*tlen
    float ac = __shfl_sync(FULLM, a1, tlen - 1);    // state 2*tlen-1
    if (l == 0) {
        float nll = -lae(ab, ac);
        if (nll > 1e29f) nll = 0.f;
        g_nll[n] = nll;
    }

    // -------- last-block final reduction --------
    __shared__ unsigned int s_old;
    __shared__ float red[NCAND];
    __syncthreads();
    __threadfence();
    if (tid == 0) s_old = atomicAdd(&g_ctr, 1u);
    __syncthreads();
    if (s_old == (unsigned)(CTCB - 1)) {
        volatile float* vnll = g_nll;
        int bb = tid;
        float lm = vnll[bb] / (float)__ldg(length + bb);
        float lc = 0.f;
#pragma unroll
        for (int k = 0; k < Kn; k++)
            lc += vnll[Bn + bb * Kn + k] / (float)__ldg(smooth_length + bb * Kn + k);
        lc *= (1.f / (float)Kn);
        float conf = g_conf[bb];
        float omc = 1.f - conf;
        float r = TAIL_C + (1.f - TAIL_C) * omc * omc;
        red[bb] = lm + ALPHA_C * r * lc;
        __syncthreads();
        for (int off = Bn / 2; off > 0; off >>= 1) {
            if (bb < off) red[bb] += red[bb + off];
            __syncthreads();
        }
        if (bb == 0) out[0] = red[0] / (float)Bn;
    }
}

// ---------------- launch ----------------
extern "C" void kernel_launch(void* const* d_in, const int* in_sizes, int n_in,
                              void* d_out, int out_size) {
    const float* preds         = (const float*)d_in[0];
    const int*   text          = (const int*)d_in[1];
    const int*   preds_size    = (const int*)d_in[2];
    const int*   length        = (const int*)d_in[3];
    const int*   smooth_text   = (const int*)d_in[4];
    const int*   smooth_length = (const int*)d_in[5];
    float* out = (float*)d_out;

    k_rowstats<<<Bn * Tn, 256>>>(preds);
    k_beam    <<<Bn, 128>>>(preds);
    k_ctc     <<<CTCB, 128>>>(preds, text, preds_size, length,
                              smooth_text, smooth_length, out);
}

// round 6
// speedup vs baseline: 1.4228x; 1.1750x over previous
#include <cuda_runtime.h>
#include <math.h>
#include <float.h>

#define Bn 128
#define Tn 64
#define Cn 6625
#define Ln 25
#define Kn 6
#define Sn (2*Ln + 1)
#define NEGF (-1e30f)
#define ALPHA_C 0.1f
#define TAIL_C 0.01f
#define NSEQ (Bn + Bn*Kn)      // 896
#define NCAND 128
#define NLAB 176               // 25 master + 150 smooth + 1 blank (slot 175)
#define FULLM 0xffffffffu
#define VRPT 7                 // 7*256*4 = 7168 >= 6625
#define CTCB (NSEQ/4)          // 224 ctc blocks
#define BCB (Bn + CTCB)        // 352 blocks in k_bc

// ---------------- device scratch ----------------
__device__ float g_logZ[Bn*Tn];
__device__ float g_m1[Bn*Tn];
__device__ float g_m2[Bn*Tn];
__device__ int   g_i1[Bn*Tn];
__device__ int   g_i2[Bn*Tn];
__device__ float g_lpb0[Bn*Tn];
__device__ float g_tbl[Bn*Tn*NCAND];    // 4MB beam candidate lp table
__device__ float g_lab[Bn*Tn*NLAB];     // 5.8MB label-slot lp table (L2 resident)
__device__ float g_conf[Bn];
__device__ float g_nll[NSEQ];
__device__ unsigned int g_ctr;

__device__ __forceinline__ float lae(float a, float b) {
    float mx = fmaxf(a, b), mn = fminf(a, b);
    return mx + __logf(1.f + __expf(mn - mx));
}
__device__ __forceinline__ float lae3(float a, float b, float c) {
    float m = fmaxf(a, fmaxf(b, c));
    return m + __logf(__expf(a - m) + __expf(b - m) + __expf(c - m));
}
__device__ __forceinline__ unsigned int fkey(float v) {
    unsigned int b = __float_as_uint(v);
    return (b & 0x80000000u) ? ~b : (b | 0x80000000u);
}

__device__ __forceinline__ int scan_idx(const float* rv, float pe, float tv,
        int tid, int a0, int nv, int rem, float target, int excl) {
    int best = 0x7fffffff;
    if (tid >= 1 && tid < a0 && pe == target && tid != excl) best = tid;
#pragma unroll
    for (int k = 0; k < VRPT; k++) {
        int idx = tid + k * 256;
        if (idx < nv) {
            int cb = a0 + (idx << 2);
#pragma unroll
            for (int j = 0; j < 4; j++) {
                int c = cb + j;
                if (c >= 1 && c != excl && rv[k*4+j] == target && c < best) best = c;
            }
        }
    }
    int ct = a0 + (nv << 2) + tid;
    if (tid < rem && tv == target && ct != excl && ct < best) best = ct;
    return best;
}
__device__ __forceinline__ float scan_max_excl(const float* rv, float pe, float tv,
        int tid, int a0, int nv, int rem, int excl) {
    float m = -FLT_MAX;
    if (tid >= 1 && tid < a0 && tid != excl) m = fmaxf(m, pe);
#pragma unroll
    for (int k = 0; k < VRPT; k++) {
        int idx = tid + k * 256;
        if (idx < nv) {
            int cb = a0 + (idx << 2);
#pragma unroll
            for (int j = 0; j < 4; j++) {
                int c = cb + j;
                if (c >= 1 && c != excl) m = fmaxf(m, rv[k*4+j]);
            }
        }
    }
    int ct = a0 + (nv << 2) + tid;
    if (tid < rem && ct != excl) m = fmaxf(m, tv);
    return m;
}

// ---------------- kernel 1: row stats ----------------
__global__ __launch_bounds__(256) void k_rowstats(const float* __restrict__ preds) {
    int row = blockIdx.x;
    const float* p = preds + (long long)row * Cn;
    int tid = threadIdx.x;
    int lane = tid & 31, wid = tid >> 5;

    if (row == 0 && tid == 0) g_ctr = 0u;

    int a0 = (4 - ((row * Cn) & 3)) & 3;
    int nv = (Cn - a0) >> 2;
    int rem = Cn - a0 - (nv << 2);
    const float4* pv = (const float4*)(p + a0);

    float rv[VRPT * 4];
    float cmx = -FLT_MAX;                 // candidate (c>=1) max

    float pe = (tid < a0) ? __ldg(p + tid) : -FLT_MAX;
    if (tid >= 1) cmx = fmaxf(cmx, pe);

    int ctail = a0 + (nv << 2) + tid;
    float tv = (tid < rem) ? __ldg(p + ctail) : -FLT_MAX;
    cmx = fmaxf(cmx, tv);

#pragma unroll
    for (int k = 0; k < VRPT; k++) {
        int idx = tid + k * 256;
        bool ok = (idx < nv);
        float4 v = ok ? __ldg(pv + idx) : make_float4(-FLT_MAX,-FLT_MAX,-FLT_MAX,-FLT_MAX);
        rv[k*4+0] = v.x; rv[k*4+1] = v.y; rv[k*4+2] = v.z; rv[k*4+3] = v.w;
        float vx = (a0 == 0 && idx == 0) ? -FLT_MAX : v.x;   // exclude class 0
        cmx = fmaxf(fmaxf(cmx, fmaxf(vx, v.y)), fmaxf(v.z, v.w));
    }

    unsigned long long key = ((unsigned long long)fkey(cmx) << 32) | (unsigned)tid;
#pragma unroll
    for (int off = 16; off > 0; off >>= 1) {
        unsigned long long o = __shfl_xor_sync(FULLM, key, off);
        key = (o > key) ? o : key;
    }
    __shared__ float s_s[8];
    __shared__ unsigned long long s_k[8];
    __shared__ float s_bmx, s_sum, s_m1, s_m2, s_loc2;
    __shared__ int s_i1, s_i2;
    __shared__ unsigned long long s_key;
    if (lane == 0) s_k[wid] = key;
    __syncthreads();
    if (wid == 0) {
        unsigned long long u = (lane < 8) ? s_k[lane] : 0ull;
#pragma unroll
        for (int off = 4; off > 0; off >>= 1) {
            unsigned long long o = __shfl_xor_sync(FULLM, u, off);
            u = (o > u) ? o : u;
        }
        if (lane == 0) s_key = u;
    }
    __syncthreads();

    int T1 = (int)(s_key & 0xFFFFFFFFull);
    if (tid == T1) {
        float m1 = cmx;
        s_m1 = m1;
        int i1 = scan_idx(rv, pe, tv, tid, a0, nv, rem, m1, -1);
        s_i1 = i1;
        s_loc2 = scan_max_excl(rv, pe, tv, tid, a0, nv, rem, i1);
        s_bmx = fmaxf(m1, __ldg(p));      // overall max = max(cand max, blank)
    }
    __syncthreads();

    float val2 = (tid == T1) ? s_loc2 : cmx;
    unsigned long long key2 = ((unsigned long long)fkey(val2) << 32) | (unsigned)tid;
#pragma unroll
    for (int off = 16; off > 0; off >>= 1) {
        unsigned long long o = __shfl_xor_sync(FULLM, key2, off);
        key2 = (o > key2) ? o : key2;
    }
    if (lane == 0) s_k[wid] = key2;
    __syncthreads();
    if (wid == 0) {
        unsigned long long u = (lane < 8) ? s_k[lane] : 0ull;
#pragma unroll
        for (int off = 4; off > 0; off >>= 1) {
            unsigned long long o = __shfl_xor_sync(FULLM, u, off);
            u = (o > u) ? o : u;
        }
        if (lane == 0) s_key = u;
    }
    __syncthreads();
    int T2 = (int)(s_key & 0xFFFFFFFFull);
    if (tid == T2) {
        float m2 = (tid == T1) ? s_loc2 : cmx;
        s_m2 = m2;
        s_i2 = scan_idx(rv, pe, tv, tid, a0, nv, rem, m2, s_i1);
    }
    __syncthreads();

    float bmx = s_bmx;
    float sum = __expf(pe - bmx) + __expf(tv - bmx);
#pragma unroll
    for (int k = 0; k < VRPT * 4; k++) sum += __expf(rv[k] - bmx);
#pragma unroll
    for (int off = 16; off > 0; off >>= 1)
        sum += __shfl_xor_sync(FULLM, sum, off);
    if (lane == 0) s_s[wid] = sum;
    __syncthreads();
    if (wid == 0) {
        float sm = (lane < 8) ? s_s[lane] : 0.f;
#pragma unroll
        for (int off = 4; off > 0; off >>= 1) sm += __shfl_xor_sync(FULLM, sm, off);
        if (lane == 0) s_sum = sm;
    }
    __syncthreads();

    if (tid == 0) {
        float lz = bmx + __logf(s_sum);
        g_logZ[row] = lz;
        g_m1[row] = s_m1;  g_i1[row] = s_i1;
        g_m2[row] = s_m2;  g_i2[row] = s_i2;
        g_lpb0[row] = __ldg(p) - lz;
    }
}

// ---------------- kernel 2: high-MLP gather of beam + label tables ----------------
__global__ __launch_bounds__(256) void k_gather2(
    const float* __restrict__ preds,
    const int* __restrict__ text,
    const int* __restrict__ smooth_text)
{
    int row = blockIdx.x;                 // b*Tn + t
    int b = row >> 6;
    const float* p = preds + (long long)row * Cn;
    float lz = g_logZ[row];

    for (int j = threadIdx.x; j < NCAND + NLAB; j += 256) {
        int ch;
        if (j < NCAND) {
            ch = (j < Tn) ? g_i1[b*Tn + j] : g_i2[b*Tn + (j - Tn)];
            g_tbl[(long long)row * NCAND + j] = __ldg(p + ch) - lz;
        } else {
            int s = j - NCAND;            // 0..175
            if (s < Ln)            ch = __ldg(text + b*Ln + s);
            else if (s < NLAB - 1) ch = __ldg(smooth_text + b*(Kn*Ln) + (s - Ln));
            else                   ch = 0;  // blank slot
            g_lab[(long long)row * NLAB + s] = __ldg(p + ch) - lz;
        }
    }
}

// ---------------- kernel 3: beam blocks + ctc warps + final ----------------
__global__ __launch_bounds__(128) void k_bc(
    const int* __restrict__ preds_size,
    const int* __restrict__ length,
    const int* __restrict__ smooth_length,
    float* __restrict__ out)
{
    int tid = threadIdx.x;
    __shared__ float stbl[Tn * NCAND];    // 32KB (beam path only)
    __shared__ float sm1[Tn], sm2[Tn], slz[Tn], slpb[Tn];
    __shared__ int   si1[Tn], si2[Tn];
    __shared__ unsigned int s_old;
    __shared__ float red[NCAND];

    if (blockIdx.x < Bn) {
        // ================= beam-1 prefix search =================
        int b = blockIdx.x;
        if (tid < Tn) {
            int r = b * Tn + tid;
            sm1[tid] = g_m1[r]; sm2[tid] = g_m2[r];
            si1[tid] = g_i1[r]; si2[tid] = g_i2[r];
            slz[tid] = g_logZ[r]; slpb[tid] = g_lpb0[r];
        }
        const float* gt = g_tbl + (long long)b * Tn * NCAND;
#pragma unroll 8
        for (int idx = tid; idx < Tn * NCAND; idx += 128) stbl[idx] = gt[idx];
        __syncthreads();

        if (tid == 0) {
            float lpb = 0.f, lpnb = NEGF;
            int last = -1, lastj = 0;
            for (int t = 0; t < Tn; t++) {
                float lp_last = (last >= 0) ? stbl[t * NCAND + lastj] : NEGF;
                float tot    = lae(lpb, lpnb);
                float new_pb = tot + slpb[t];
                float rep    = (last >= 0) ? (lpnb + lp_last) : NEGF;
                float keep   = lae(new_pb, rep);
                float lpm1 = sm1[t] - slz[t];
                float lpm2 = sm2[t] - slz[t];
                float best_ext; int best_c, best_j;
                if (si1[t] != last) {
                    best_ext = tot + lpm1; best_c = si1[t]; best_j = t;
                } else {
                    float cA = lpb + lpm1;
                    float cB = tot + lpm2;
                    if (cA > cB || (cA == cB && last < si2[t])) {
                        best_ext = cA; best_c = last; best_j = t;
                    } else {
                        best_ext = cB; best_c = si2[t]; best_j = Tn + t;
                    }
                }
                bool take = best_ext > keep;
                lpb   = take ? NEGF     : new_pb;
                lpnb  = take ? best_ext : rep;
                last  = take ? best_c   : last;
                lastj = take ? best_j   : lastj;
            }
            g_conf[b] = __expf(lae(lpb, lpnb) / (float)Tn);
        }
    } else {
        // ================= CTC: warp per sequence, L2-hot coalesced loads ========
        int warp = tid >> 5, l = tid & 31;
        int n = (blockIdx.x - Bn) * 4 + warp;     // < 896

        int b, tlen, ilen, sb;
        if (n < Bn) {
            b = n; sb = 0;
            tlen = __ldg(length + n); ilen = __ldg(preds_size + n);
        } else {
            int m = n - Bn;
            b = m / Kn;
            sb = Ln + (m - b * Kn) * Ln;          // 25 + k*25
            tlen = __ldg(smooth_length + m); ilen = Tn;
        }

        const float* labp = g_lab + (long long)(b * Tn) * NLAB + sb + l;  // lane slot
        const float* blkp = g_lab + (long long)(b * Tn) * NLAB + (NLAB - 1);

        // char values per lane (already normalized); identify repeats via slot char?
        // need skip flag: ext[2l+1]=lab[l] vs lab[l-1]: compare char *values* is wrong;
        // compare char ids: reload from the original label arrays is avoided by
        // comparing lp values? unsafe. Load char ids directly (tiny, L2-hot).
        // (labels: slot sb+l of b's label id arrays)
        bool ldok = (l < Ln);
        bool v0 = (l <= 25), v1 = (l <= 24);

        // char ids for skip flags: use g_lab trick is unsafe; fetch ids cheaply:
        // master: text, smooth: smooth_text. Kept tiny/cached.
        // (passed via constant-like global pointers not available here; use lp equality
        //  fallback is unsafe -> we instead stored ids? Simplest: compare via separate load)
        // --- ids are loaded from the id tables below ---
        extern __device__ int g_dummy;   // (placeholder, unused)

        // load char ids
        // Note: we re-derive them exactly as gather2 did.
        // text/smooth_text pointers are passed through launch params of k_gather2 only,
        // so here we read ids from a compact copy written by gather2? To avoid extra
        // plumbing we recompute skip flags from ids loaded via __ldg on the tables
        // passed as kernel arguments (see k_bc2 signature below).
        // -- this branch replaced by k_bc2 --
        (void)ldok; (void)v0; (void)v1; (void)tlen; (void)ilen; (void)labp; (void)blkp;
    }
    (void)s_old; (void)red; (void)stbl; (void)sm1; (void)sm2; (void)slz; (void)slpb;
    (void)si1; (void)si2; (void)preds_size; (void)length; (void)smooth_length; (void)out;
}

// ---------------- kernel 3 (real): beam + ctc + final ----------------
__global__ __launch_bounds__(128) void k_bc2(
    const int* __restrict__ text,
    const int* __restrict__ preds_size,
    const int* __restrict__ length,
    const int* __restrict__ smooth_text,
    const int* __restrict__ smooth_length,
    float* __restrict__ out)
{
    int tid = threadIdx.x;
    __shared__ float stbl[Tn * NCAND];
    __shared__ float sm1[Tn], sm2[Tn], slz[Tn], slpb[Tn];
    __shared__ int   si1[Tn], si2[Tn];
    __shared__ unsigned int s_old;
    __shared__ float red[NCAND];

    if (blockIdx.x < Bn) {
        int b = blockIdx.x;
        if (tid < Tn) {
            int r = b * Tn + tid;
            sm1[tid] = g_m1[r]; sm2[tid] = g_m2[r];
            si1[tid] = g_i1[r]; si2[tid] = g_i2[r];
            slz[tid] = g_logZ[r]; slpb[tid] = g_lpb0[r];
        }
        const float* gt = g_tbl + (long long)b * Tn * NCAND;
#pragma unroll 8
        for (int idx = tid; idx < Tn * NCAND; idx += 128) stbl[idx] = gt[idx];
        __syncthreads();

        if (tid == 0) {
            float lpb = 0.f, lpnb = NEGF;
            int last = -1, lastj = 0;
            for (int t = 0; t < Tn; t++) {
                float lp_last = (last >= 0) ? stbl[t * NCAND + lastj] : NEGF;
                float tot    = lae(lpb, lpnb);
                float new_pb = tot + slpb[t];
                float rep    = (last >= 0) ? (lpnb + lp_last) : NEGF;
                float keep   = lae(new_pb, rep);
                float lpm1 = sm1[t] - slz[t];
                float lpm2 = sm2[t] - slz[t];
                float best_ext; int best_c, best_j;
                if (si1[t] != last) {
                    best_ext = tot + lpm1; best_c = si1[t]; best_j = t;
                } else {
                    float cA = lpb + lpm1;
                    float cB = tot + lpm2;
                    if (cA > cB || (cA == cB && last < si2[t])) {
                        best_ext = cA; best_c = last; best_j = t;
                    } else {
                        best_ext = cB; best_c = si2[t]; best_j = Tn + t;
                    }
                }
                bool take = best_ext > keep;
                lpb   = take ? NEGF     : new_pb;
                lpnb  = take ? best_ext : rep;
                last  = take ? best_c   : last;
                lastj = take ? best_j   : lastj;
            }
            g_conf[b] = __expf(lae(lpb, lpnb) / (float)Tn);
        }
    } else {
        int warp = tid >> 5, l = tid & 31;
        int n = (blockIdx.x - Bn) * 4 + warp;

        int b, tlen, ilen, sb;
        const int* lab;
        if (n < Bn) {
            b = n; sb = 0; lab = text + n * Ln;
            tlen = __ldg(length + n); ilen = __ldg(preds_size + n);
        } else {
            int m = n - Bn;
            b = m / Kn;
            int k = m - b * Kn;
            sb = Ln + k * Ln;
            lab = smooth_text + m * Ln;
            tlen = __ldg(smooth_length + m); ilen = Tn;
        }

        int lab_l = (l < Ln) ? __ldg(lab + l) : 0;
        int lab_p = __shfl_up_sync(FULLM, lab_l, 1);
        bool skip1 = (l >= 1) && (l < Ln) && (lab_l != lab_p);
        bool v0 = (l <= 25), v1 = (l <= 24);
        bool ldok = (l < Ln);

        const float* labp = g_lab + (long long)(b * Tn) * NLAB + sb + l;
        const float* blkp = g_lab + (long long)(b * Tn) * NLAB + (NLAB - 1);

        float c0  = ldok ? __ldg(labp) : NEGF;    // normalized lp of lane's char, t=0
        float bl0 = __ldg(blkp);
        float a0 = (l == 0) ? bl0 : NEGF;
        float a1 = (l == 0) ? c0  : NEGF;

        float pf[8], pblk[8];
#pragma unroll
        for (int q = 0; q < 8; q++) {
            pf[q]   = ldok ? __ldg(labp + (1 + q) * NLAB) : 0.f;
            pblk[q] = __ldg(blkp + (1 + q) * NLAB);
        }

#pragma unroll 4
        for (int t = 1; t < Tn; t++) {
            float raw  = pf[(t - 1) & 7];
            float lpbt = pblk[(t - 1) & 7];
            if (t + 8 < Tn) {
                if (ldok) pf[(t - 1) & 7] = __ldg(labp + (t + 8) * NLAB);
                pblk[(t - 1) & 7] = __ldg(blkp + (t + 8) * NLAB);
            }
            float p1 = __shfl_up_sync(FULLM, a1, 1);
            if (l == 0) p1 = NEGF;

            float tot0 = lae(a0, p1);
            float tot1 = lae3(a1, a0, skip1 ? p1 : NEGF);
            float n0 = tot0 + lpbt;
            float n1 = tot1 + raw;
            bool act = (t < ilen);
            a0 = act ? (v0 ? n0 : NEGF) : a0;
            a1 = act ? (v1 ? n1 : NEGF) : a1;
        }

        float ab = __shfl_sync(FULLM, a0, tlen);
        float ac = __shfl_sync(FULLM, a1, tlen - 1);
        if (l == 0) {
            float nll = -lae(ab, ac);
            if (nll > 1e29f) nll = 0.f;
            g_nll[n] = nll;
        }
    }

    // -------- last-block final reduction --------
    __syncthreads();
    __threadfence();
    if (tid == 0) s_old = atomicAdd(&g_ctr, 1u);
    __syncthreads();
    if (s_old == (unsigned)(BCB - 1)) {
        volatile float* vnll  = g_nll;
        volatile float* vconf = g_conf;
        int bb = tid;
        float lm = vnll[bb] / (float)__ldg(length + bb);
        float lc = 0.f;
#pragma unroll
        for (int k = 0; k < Kn; k++)
            lc += vnll[Bn + bb * Kn + k] / (float)__ldg(smooth_length + bb * Kn + k);
        lc *= (1.f / (float)Kn);
        float conf = vconf[bb];
        float omc = 1.f - conf;
        float r = TAIL_C + (1.f - TAIL_C) * omc * omc;
        red[bb] = lm + ALPHA_C * r * lc;
        __syncthreads();
        for (int off = Bn / 2; off > 0; off >>= 1) {
            if (bb < off) red[bb] += red[bb + off];
            __syncthreads();
        }
        if (bb == 0) out[0] = red[0] / (float)Bn;
    }
}

// ---------------- launch ----------------
extern "C" void kernel_launch(void* const* d_in, const int* in_sizes, int n_in,
                              void* d_out, int out_size) {
    const float* preds         = (const float*)d_in[0];
    const int*   text          = (const int*)d_in[1];
    const int*   preds_size    = (const int*)d_in[2];
    const int*   length        = (const int*)d_in[3];
    const int*   smooth_text   = (const int*)d_in[4];
    const int*   smooth_length = (const int*)d_in[5];
    float* out = (float*)d_out;

    k_rowstats<<<Bn * Tn, 256>>>(preds);
    k_gather2 <<<Bn * Tn, 256>>>(preds, text, smooth_text);
    k_bc2     <<<BCB, 128>>>(text, preds_size, length,
                             smooth_text, smooth_length, out);
}

// round 7
// speedup vs baseline: 1.5543x; 1.0924x over previous
#include <cuda_runtime.h>
#include <math.h>
#include <float.h>

#define Bn 128
#define Tn 64
#define Cn 6625
#define Ln 25
#define Kn 6
#define NEGF (-1e30f)
#define ALPHA_C 0.1f
#define TAIL_C 0.01f
#define NSEQ (Bn + Bn*Kn)      // 896
#define NCAND 128
#define NLAB 176               // 25 master + 150 smooth + 1 blank (slot 175)
#define FULLM 0xffffffffu
#define VRPT 7                 // 7*256*4 = 7168 >= 6625
#define CTCB (NSEQ/4)          // 224 ctc blocks
#define BCB (Bn + CTCB)        // 352 blocks in k_bc2

// ---------------- device scratch ----------------
__device__ float g_logZ[Bn*Tn];
__device__ float g_m1[Bn*Tn];
__device__ float g_m2[Bn*Tn];
__device__ int   g_i1[Bn*Tn];
__device__ int   g_i2[Bn*Tn];
__device__ float g_lpb0[Bn*Tn];
__device__ float g_tbl[Bn*Tn*NCAND];    // 4MB beam candidate lp table
__device__ float g_lab[Bn*Tn*NLAB];     // 5.8MB label-slot lp table (L2 resident)
__device__ float g_conf[Bn];
__device__ float g_nll[NSEQ];
__device__ unsigned int g_ctr;

__device__ __forceinline__ float lae(float a, float b) {
    float mx = fmaxf(a, b), mn = fminf(a, b);
    return mx + __logf(1.f + __expf(mn - mx));
}
__device__ __forceinline__ float lae3(float a, float b, float c) {
    float m = fmaxf(a, fmaxf(b, c));
    return m + __logf(__expf(a - m) + __expf(b - m) + __expf(c - m));
}
__device__ __forceinline__ unsigned int fkey(float v) {
    unsigned int b = __float_as_uint(v);
    return (b & 0x80000000u) ? ~b : (b | 0x80000000u);
}

// owner-thread rescan (reloads from gmem; L1/L2-hot): smallest class index
// among this thread's elements with value == target, c>=1, c != excl
__device__ __noinline__ int rescan_idx(const float* __restrict__ p,
        int tid, int a0, int nv, int rem, float target, int excl) {
    const float4* pv = (const float4*)(p + a0);
    int best = 0x7fffffff;
    if (tid >= 1 && tid < a0 && __ldg(p + tid) == target && tid != excl) best = tid;
    for (int k = 0; k < VRPT; k++) {
        int idx = tid + k * 256;
        if (idx < nv) {
            float4 v = __ldg(pv + idx);
            int cb = a0 + (idx << 2);
            if (cb >= 1 && cb != excl && v.x == target && cb < best) best = cb;
            if (cb+1 != excl && v.y == target && cb+1 < best) best = cb+1;
            if (cb+2 != excl && v.z == target && cb+2 < best) best = cb+2;
            if (cb+3 != excl && v.w == target && cb+3 < best) best = cb+3;
        }
    }
    int ct = a0 + (nv << 2) + tid;
    if (tid < rem && __ldg(p + ct) == target && ct != excl && ct < best) best = ct;
    return best;
}
// owner-thread rescan: max over this thread's elements with c>=1, c != excl
__device__ __noinline__ float rescan_max_excl(const float* __restrict__ p,
        int tid, int a0, int nv, int rem, int excl) {
    const float4* pv = (const float4*)(p + a0);
    float m = -FLT_MAX;
    if (tid >= 1 && tid < a0 && tid != excl) m = fmaxf(m, __ldg(p + tid));
    for (int k = 0; k < VRPT; k++) {
        int idx = tid + k * 256;
        if (idx < nv) {
            float4 v = __ldg(pv + idx);
            int cb = a0 + (idx << 2);
            if (cb >= 1 && cb != excl) m = fmaxf(m, v.x);
            if (cb+1 != excl) m = fmaxf(m, v.y);
            if (cb+2 != excl) m = fmaxf(m, v.z);
            if (cb+3 != excl) m = fmaxf(m, v.w);
        }
    }
    int ct = a0 + (nv << 2) + tid;
    if (tid < rem && ct != excl) m = fmaxf(m, __ldg(p + ct));
    return m;
}

// ---- kernel 1: streaming row stats (direct exp-sum, no staging) + label gather ----
__global__ __launch_bounds__(256) void k_rowstats(
    const float* __restrict__ preds,
    const int* __restrict__ text,
    const int* __restrict__ smooth_text)
{
    int row = blockIdx.x;
    const float* p = preds + (long long)row * Cn;
    int tid = threadIdx.x;
    int lane = tid & 31, wid = tid >> 5;

    if (row == 0 && tid == 0) g_ctr = 0u;

    int a0 = (4 - ((row * Cn) & 3)) & 3;
    int nv = (Cn - a0) >> 2;
    int rem = Cn - a0 - (nv << 2);
    const float4* pv = (const float4*)(p + a0);

    float sum0 = 0.f, sum1 = 0.f;
    float cmx = -FLT_MAX;                 // candidate (c>=1) max

    // peel scalars (c = tid < a0 <= 3)
    {
        float pe = (tid < a0) ? __ldg(p + tid) : NEGF;
        sum0 += __expf(pe);               // exp(-1e30) -> 0
        if (tid >= 1) cmx = fmaxf(cmx, pe);
    }
    // tail scalars
    {
        int ct = a0 + (nv << 2) + tid;
        float tv = (tid < rem) ? __ldg(p + ct) : NEGF;
        sum1 += __expf(tv);
        cmx = fmaxf(cmx, tv);
    }
    // vector body
#pragma unroll
    for (int k = 0; k < VRPT; k++) {
        int idx = tid + k * 256;
        bool ok = (idx < nv);
        float4 v = ok ? __ldg(pv + idx) : make_float4(NEGF, NEGF, NEGF, NEGF);
        sum0 += __expf(v.x) + __expf(v.y);
        sum1 += __expf(v.z) + __expf(v.w);
        float vx = (a0 == 0 && idx == 0) ? NEGF : v.x;   // exclude class 0
        cmx = fmaxf(fmaxf(cmx, fmaxf(vx, v.y)), fmaxf(v.z, v.w));
    }
    float sum = sum0 + sum1;

    // block reduce: sum + candidate argmax owner
    unsigned long long key = ((unsigned long long)fkey(cmx) << 32) | (unsigned)tid;
#pragma unroll
    for (int off = 16; off > 0; off >>= 1) {
        sum += __shfl_xor_sync(FULLM, sum, off);
        unsigned long long o = __shfl_xor_sync(FULLM, key, off);
        key = (o > key) ? o : key;
    }
    __shared__ float s_s[8];
    __shared__ unsigned long long s_k[8];
    __shared__ float s_m1, s_m2, s_loc2, s_lz;
    __shared__ int s_i1, s_i2;
    __shared__ unsigned long long s_key;
    if (lane == 0) { s_s[wid] = sum; s_k[wid] = key; }
    __syncthreads();
    if (wid == 0) {
        float sm = (lane < 8) ? s_s[lane] : 0.f;
        unsigned long long u = (lane < 8) ? s_k[lane] : 0ull;
#pragma unroll
        for (int off = 4; off > 0; off >>= 1) {
            sm += __shfl_xor_sync(FULLM, sm, off);
            unsigned long long o = __shfl_xor_sync(FULLM, u, off);
            u = (o > u) ? o : u;
        }
        if (lane == 0) { s_lz = __logf(sm); s_key = u; }
    }
    __syncthreads();

    int T1 = (int)(s_key & 0xFFFFFFFFull);
    if (tid == T1) {
        s_m1 = cmx;
        int i1 = rescan_idx(p, tid, a0, nv, rem, cmx, -1);
        s_i1 = i1;
        s_loc2 = rescan_max_excl(p, tid, a0, nv, rem, i1);
    }
    __syncthreads();

    // phase 2: second max
    float val2 = (tid == T1) ? s_loc2 : cmx;
    unsigned long long key2 = ((unsigned long long)fkey(val2) << 32) | (unsigned)tid;
#pragma unroll
    for (int off = 16; off > 0; off >>= 1) {
        unsigned long long o = __shfl_xor_sync(FULLM, key2, off);
        key2 = (o > key2) ? o : key2;
    }
    if (lane == 0) s_k[wid] = key2;
    __syncthreads();
    if (wid == 0) {
        unsigned long long u = (lane < 8) ? s_k[lane] : 0ull;
#pragma unroll
        for (int off = 4; off > 0; off >>= 1) {
            unsigned long long o = __shfl_xor_sync(FULLM, u, off);
            u = (o > u) ? o : u;
        }
        if (lane == 0) s_key = u;
    }
    __syncthreads();
    int T2 = (int)(s_key & 0xFFFFFFFFull);
    if (tid == T2) {
        float m2 = (tid == T1) ? s_loc2 : cmx;
        s_m2 = m2;
        s_i2 = rescan_idx(p, tid, a0, nv, rem, m2, s_i1);
    }
    __syncthreads();

    float lz = s_lz;
    if (tid == 0) {
        g_logZ[row] = lz;
        g_m1[row] = s_m1;  g_i1[row] = s_i1;
        g_m2[row] = s_m2;  g_i2[row] = s_i2;
        g_lpb0[row] = __ldg(p) - lz;
    }

    // fused label-table gather (row is L1-hot)
    if (tid < NLAB) {
        int b = row >> 6;
        int ch;
        if (tid < Ln)            ch = __ldg(text + b * Ln + tid);
        else if (tid < NLAB - 1) ch = __ldg(smooth_text + b * (Kn * Ln) + (tid - Ln));
        else                     ch = 0;
        g_lab[(long long)row * NLAB + tid] = __ldg(p + ch) - lz;
    }
}

// ---------------- kernel 2: beam candidate table gather ----------------
__global__ __launch_bounds__(NCAND) void k_gather(const float* __restrict__ preds) {
    int row = blockIdx.x;
    int j   = threadIdx.x;
    int b   = row >> 6;
    int ch  = (j < Tn) ? g_i1[b*Tn + j] : g_i2[b*Tn + (j - Tn)];
    g_tbl[(long long)row * NCAND + j] =
        __ldg(preds + (long long)row * Cn + ch) - g_logZ[row];
}

// ---------------- kernel 3: beam blocks + ctc warps + final ----------------
__global__ __launch_bounds__(128) void k_bc2(
    const int* __restrict__ text,
    const int* __restrict__ preds_size,
    const int* __restrict__ length,
    const int* __restrict__ smooth_text,
    const int* __restrict__ smooth_length,
    float* __restrict__ out)
{
    int tid = threadIdx.x;
    __shared__ float stbl[Tn * NCAND];
    __shared__ float sm1[Tn], sm2[Tn], slz[Tn], slpb[Tn];
    __shared__ int   si1[Tn], si2[Tn];
    __shared__ unsigned int s_old;
    __shared__ float red[NCAND];

    if (blockIdx.x < Bn) {
        int b = blockIdx.x;
        if (tid < Tn) {
            int r = b * Tn + tid;
            sm1[tid] = g_m1[r]; sm2[tid] = g_m2[r];
            si1[tid] = g_i1[r]; si2[tid] = g_i2[r];
            slz[tid] = g_logZ[r]; slpb[tid] = g_lpb0[r];
        }
        const float* gt = g_tbl + (long long)b * Tn * NCAND;
#pragma unroll 8
        for (int idx = tid; idx < Tn * NCAND; idx += 128) stbl[idx] = gt[idx];
        __syncthreads();

        if (tid == 0) {
            float lpb = 0.f, lpnb = NEGF;
            int last = -1, lastj = 0;
            for (int t = 0; t < Tn; t++) {
                float lp_last = (last >= 0) ? stbl[t * NCAND + lastj] : NEGF;
                float tot    = lae(lpb, lpnb);
                float new_pb = tot + slpb[t];
                float rep    = (last >= 0) ? (lpnb + lp_last) : NEGF;
                float keep   = lae(new_pb, rep);
                float lpm1 = sm1[t] - slz[t];
                float lpm2 = sm2[t] - slz[t];
                float best_ext; int best_c, best_j;
                if (si1[t] != last) {
                    best_ext = tot + lpm1; best_c = si1[t]; best_j = t;
                } else {
                    float cA = lpb + lpm1;
                    float cB = tot + lpm2;
                    if (cA > cB || (cA == cB && last < si2[t])) {
                        best_ext = cA; best_c = last; best_j = t;
                    } else {
                        best_ext = cB; best_c = si2[t]; best_j = Tn + t;
                    }
                }
                bool take = best_ext > keep;
                lpb   = take ? NEGF     : new_pb;
                lpnb  = take ? best_ext : rep;
                last  = take ? best_c   : last;
                lastj = take ? best_j   : lastj;
            }
            g_conf[b] = __expf(lae(lpb, lpnb) / (float)Tn);
        }
    } else {
        int warp = tid >> 5, l = tid & 31;
        int n = (blockIdx.x - Bn) * 4 + warp;

        int b, tlen, ilen, sb;
        const int* lab;
        if (n < Bn) {
            b = n; sb = 0; lab = text + n * Ln;
            tlen = __ldg(length + n); ilen = __ldg(preds_size + n);
        } else {
            int m = n - Bn;
            b = m / Kn;
            int k = m - b * Kn;
            sb = Ln + k * Ln;
            lab = smooth_text + m * Ln;
            tlen = __ldg(smooth_length + m); ilen = Tn;
        }

        int lab_l = (l < Ln) ? __ldg(lab + l) : 0;
        int lab_p = __shfl_up_sync(FULLM, lab_l, 1);
        bool skip1 = (l >= 1) && (l < Ln) && (lab_l != lab_p);
        bool v0 = (l <= 25), v1 = (l <= 24);
        bool ldok = (l < Ln);

        const float* labp = g_lab + (long long)(b * Tn) * NLAB + sb + l;
        const float* blkp = g_lab + (long long)(b * Tn) * NLAB + (NLAB - 1);

        float c0  = ldok ? __ldg(labp) : NEGF;
        float bl0 = __ldg(blkp);
        float a0 = (l == 0) ? bl0 : NEGF;
        float a1 = (l == 0) ? c0  : NEGF;

        float pf[8], pblk[8];
#pragma unroll
        for (int q = 0; q < 8; q++) {
            pf[q]   = ldok ? __ldg(labp + (1 + q) * NLAB) : 0.f;
            pblk[q] = __ldg(blkp + (1 + q) * NLAB);
        }

#pragma unroll 4
        for (int t = 1; t < Tn; t++) {
            float raw  = pf[(t - 1) & 7];
            float lpbt = pblk[(t - 1) & 7];
            if (t + 8 < Tn) {
                if (ldok) pf[(t - 1) & 7] = __ldg(labp + (t + 8) * NLAB);
                pblk[(t - 1) & 7] = __ldg(blkp + (t + 8) * NLAB);
            }
            float p1 = __shfl_up_sync(FULLM, a1, 1);
            if (l == 0) p1 = NEGF;

            float tot0 = lae(a0, p1);
            float tot1 = lae3(a1, a0, skip1 ? p1 : NEGF);
            float n0 = tot0 + lpbt;
            float n1 = tot1 + raw;
            bool act = (t < ilen);
            a0 = act ? (v0 ? n0 : NEGF) : a0;
            a1 = act ? (v1 ? n1 : NEGF) : a1;
        }

        float ab = __shfl_sync(FULLM, a0, tlen);
        float ac = __shfl_sync(FULLM, a1, tlen - 1);
        if (l == 0) {
            float nll = -lae(ab, ac);
            if (nll > 1e29f) nll = 0.f;
            g_nll[n] = nll;
        }
    }

    // -------- last-block final reduction --------
    __syncthreads();
    __threadfence();
    if (tid == 0) s_old = atomicAdd(&g_ctr, 1u);
    __syncthreads();
    if (s_old == (unsigned)(BCB - 1)) {
        volatile float* vnll  = g_nll;
        volatile float* vconf = g_conf;
        int bb = tid;
        float lm = vnll[bb] / (float)__ldg(length + bb);
        float lc = 0.f;
#pragma unroll
        for (int k = 0; k < Kn; k++)
            lc += vnll[Bn + bb * Kn + k] / (float)__ldg(smooth_length + bb * Kn + k);
        lc *= (1.f / (float)Kn);
        float conf = vconf[bb];
        float omc = 1.f - conf;
        float r = TAIL_C + (1.f - TAIL_C) * omc * omc;
        red[bb] = lm + ALPHA_C * r * lc;
        __syncthreads();
        for (int off = Bn / 2; off > 0; off >>= 1) {
            if (bb < off) red[bb] += red[bb + off];
            __syncthreads();
        }
        if (bb == 0) out[0] = red[0] / (float)Bn;
    }
}

// ---------------- launch ----------------
extern "C" void kernel_launch(void* const* d_in, const int* in_sizes, int n_in,
                              void* d_out, int out_size) {
    const float* preds         = (const float*)d_in[0];
    const int*   text          = (const int*)d_in[1];
    const int*   preds_size    = (const int*)d_in[2];
    const int*   length        = (const int*)d_in[3];
    const int*   smooth_text   = (const int*)d_in[4];
    const int*   smooth_length = (const int*)d_in[5];
    float* out = (float*)d_out;

    k_rowstats<<<Bn * Tn, 256>>>(preds, text, smooth_text);
    k_gather  <<<Bn * Tn, NCAND>>>(preds);
    k_bc2     <<<BCB, 128>>>(text, preds_size, length,
                             smooth_text, smooth_length, out);
}